// round 1
// baseline (speedup 1.0000x reference)
#include <cuda_runtime.h>
#include <cuda_bf16.h>
#include <math.h>

// Problem constants (fixed by the dataset)
#define NN 100000
#define NE 1600000
#define NG 1000
#define FIN 10
#define FH  128
#define NB  ((NN + 1023) / 1024)   // scan blocks = 98

// ---------------- scratch (device globals; no cudaMalloc allowed) -----------
__device__ int   d_cnt[NN];            // in-degree (edges only)
__device__ int   d_cur[NN];            // scatter cursor
__device__ int   d_off[NN];            // CSR row offsets (exclusive scan of cnt)
__device__ int   d_csr[NE];            // CSR column (src) indices, grouped by dst
__device__ float d_dinv[NN];           // rsqrt(deg), deg = indeg + 1 (self loop)
__device__ float d_aggx[NN * FIN];     // 10-dim aggregated input
__device__ float d_h1[NN * FH];        // layer-1 activations
__device__ float d_agg[NN * FH];       // 128-dim aggregation of h1
__device__ float d_h2[NN * FH];        // layer-2 activations
__device__ float d_gm[NG * FH];        // per-graph mean
__device__ int   d_gs[NG + 1];         // graph start offsets in sorted batch
__device__ int   d_bsum[NB];           // scan partials
__device__ int   d_is64;               // 1 if edge_index/batch are int64

// ---------------- index dtype detection -------------------------------------
__global__ void k_detect(const int* __restrict__ ei) {
    __shared__ int nz;
    if (threadIdx.x == 0) nz = 0;
    __syncthreads();
    // If the data is int64 (values < 2^31), every odd 32-bit word is zero.
    for (int i = threadIdx.x; i < 2048; i += blockDim.x)
        if ((i & 1) && ei[i] != 0) atomicOr(&nz, 1);
    __syncthreads();
    if (threadIdx.x == 0) d_is64 = (nz == 0) ? 1 : 0;
}

__device__ __forceinline__ int ld_src(const int* ei, int e) {
    return d_is64 ? ei[2 * e] : ei[e];
}
__device__ __forceinline__ int ld_dst(const int* ei, int e) {
    return d_is64 ? ei[2 * (NE + e)] : ei[NE + e];
}

// ---------------- CSR build --------------------------------------------------
__global__ void k_zero() {
    int i = blockIdx.x * blockDim.x + threadIdx.x;
    if (i < NN) { d_cnt[i] = 0; d_cur[i] = 0; }
}

__global__ void k_hist(const int* __restrict__ ei) {
    int e = blockIdx.x * blockDim.x + threadIdx.x;
    if (e < NE) atomicAdd(&d_cnt[ld_dst(ei, e)], 1);
}

__global__ void k_scan1() {
    __shared__ int s[1024];
    int i = blockIdx.x * 1024 + threadIdx.x;
    int v = (i < NN) ? d_cnt[i] : 0;
    s[threadIdx.x] = v;
    __syncthreads();
    for (int o = 1; o < 1024; o <<= 1) {
        int add = (threadIdx.x >= o) ? s[threadIdx.x - o] : 0;
        __syncthreads();
        s[threadIdx.x] += add;
        __syncthreads();
    }
    if (i < NN) d_off[i] = s[threadIdx.x] - v;   // exclusive, local
    if (threadIdx.x == 1023) d_bsum[blockIdx.x] = s[1023];
}

__global__ void k_scan2() {
    if (threadIdx.x == 0 && blockIdx.x == 0) {
        int run = 0;
        for (int b = 0; b < NB; b++) { int t = d_bsum[b]; d_bsum[b] = run; run += t; }
    }
}

__global__ void k_scan3() {
    int i = blockIdx.x * 1024 + threadIdx.x;
    if (i < NN) d_off[i] += d_bsum[blockIdx.x];
}

__global__ void k_dinv() {
    int i = blockIdx.x * blockDim.x + threadIdx.x;
    if (i < NN) d_dinv[i] = rsqrtf((float)(d_cnt[i] + 1));
}

__global__ void k_scatter(const int* __restrict__ ei) {
    int e = blockIdx.x * blockDim.x + threadIdx.x;
    if (e < NE) {
        int s = ld_src(ei, e);
        int d = ld_dst(ei, e);
        int pos = d_off[d] + atomicAdd(&d_cur[d], 1);
        d_csr[pos] = s;
    }
}

// ---------------- layer 1: aggregate x (10-dim), then linear ----------------
__global__ void k_aggx(const float* __restrict__ x) {
    int n = blockIdx.x * blockDim.x + threadIdx.x;
    if (n >= NN) return;
    float acc[FIN];
#pragma unroll
    for (int f = 0; f < FIN; f++) acc[f] = 0.f;
    int beg = d_off[n], len = d_cnt[n];
    for (int j = 0; j < len; j++) {
        int s = d_csr[beg + j];
        float w = d_dinv[s];
        const float* xr = x + s * FIN;
#pragma unroll
        for (int f = 0; f < FIN; f++) acc[f] += xr[f] * w;
    }
    float di = d_dinv[n];
    float d2 = di * di;
    const float* xn = x + n * FIN;
#pragma unroll
    for (int f = 0; f < FIN; f++)
        d_aggx[n * FIN + f] = di * acc[f] + d2 * xn[f];
}

__global__ void __launch_bounds__(256) k_lin1(const float* __restrict__ W1,
                                              const float* __restrict__ b1) {
    __shared__ float sW[FIN * FH];   // 5 KB
    for (int i = threadIdx.x; i < FIN * FH; i += 256) sW[i] = W1[i];
    __syncthreads();
    int idx = blockIdx.x * 256 + threadIdx.x;   // one thread per (node, feature)
    int n = idx >> 7;
    int f = idx & 127;
    if (n >= NN) return;
    const float* a = d_aggx + n * FIN;   // broadcast across the warp
    float acc = b1[f];
#pragma unroll
    for (int k = 0; k < FIN; k++) acc += a[k] * sW[k * FH + f];
    d_h1[n * FH + f] = fmaxf(acc, 0.f);
}

// ---------------- layer 2: 128-dim aggregation (warp per node) --------------
__global__ void __launch_bounds__(256) k_agg128() {
    int warp = (blockIdx.x * blockDim.x + threadIdx.x) >> 5;
    int lane = threadIdx.x & 31;
    if (warp >= NN) return;
    int n = warp;
    const float4* H = (const float4*)d_h1;
    float4 acc = make_float4(0.f, 0.f, 0.f, 0.f);
    int beg = d_off[n], len = d_cnt[n];
#pragma unroll 2
    for (int j = 0; j < len; j++) {
        int s = d_csr[beg + j];
        float w = d_dinv[s];
        float4 v = H[s * 32 + lane];
        acc.x += v.x * w; acc.y += v.y * w; acc.z += v.z * w; acc.w += v.w * w;
    }
    float di = d_dinv[n];
    float d2 = di * di;
    float4 sv = H[n * 32 + lane];
    float4 r;
    r.x = di * acc.x + d2 * sv.x;
    r.y = di * acc.y + d2 * sv.y;
    r.z = di * acc.z + d2 * sv.z;
    r.w = di * acc.w + d2 * sv.w;
    ((float4*)d_agg)[n * 32 + lane] = r;
}

// ---------------- layer 2 linear: [NN,128] @ [128,128], bias + relu ---------
// Block: 256 threads, 32 rows x 128 cols tile, 4x4 register micro-tile.
__global__ void __launch_bounds__(256) k_lin2(const float* __restrict__ W2,
                                              const float* __restrict__ b2) {
    __shared__ float sW[64 * FH];   // 32 KB K-chunk of W2
    const int tx = threadIdx.x & 31;   // cols 4*tx..4*tx+3
    const int ty = threadIdx.x >> 5;   // rows ty*4..ty*4+3
    const int row0 = blockIdx.x * 32 + ty * 4;
    const float* A = d_agg;
    float acc[4][4];
#pragma unroll
    for (int r = 0; r < 4; r++)
#pragma unroll
        for (int c = 0; c < 4; c++) acc[r][c] = 0.f;

    for (int kc = 0; kc < FH; kc += 64) {
        const float4* Wv = (const float4*)(W2 + kc * FH);
        float4* sWv = (float4*)sW;
#pragma unroll
        for (int i = threadIdx.x; i < 64 * 32; i += 256) sWv[i] = Wv[i];
        __syncthreads();

#pragma unroll 4
        for (int k = 0; k < 64; k += 4) {
            float4 a[4];
#pragma unroll
            for (int r = 0; r < 4; r++)
                a[r] = *(const float4*)(A + (row0 + r) * FH + kc + k);
#pragma unroll
            for (int kk = 0; kk < 4; kk++) {
                float4 wv = *(const float4*)(sW + (k + kk) * FH + tx * 4);
#pragma unroll
                for (int r = 0; r < 4; r++) {
                    float av = (kk == 0) ? a[r].x : (kk == 1) ? a[r].y
                             : (kk == 2) ? a[r].z : a[r].w;
                    acc[r][0] += av * wv.x;
                    acc[r][1] += av * wv.y;
                    acc[r][2] += av * wv.z;
                    acc[r][3] += av * wv.w;
                }
            }
        }
        __syncthreads();
    }

    float4 bb = *(const float4*)(b2 + tx * 4);
#pragma unroll
    for (int r = 0; r < 4; r++) {
        float4 o;
        o.x = fmaxf(acc[r][0] + bb.x, 0.f);
        o.y = fmaxf(acc[r][1] + bb.y, 0.f);
        o.z = fmaxf(acc[r][2] + bb.z, 0.f);
        o.w = fmaxf(acc[r][3] + bb.w, 0.f);
        *(float4*)(d_h2 + (row0 + r) * FH + tx * 4) = o;
    }
}

// ---------------- pooling + MLP ----------------------------------------------
__global__ void k_gstart(const int* __restrict__ batch) {
    int g = blockIdx.x * blockDim.x + threadIdx.x;
    if (g > NG) return;
    int lo = 0, hi = NN;
    int is64 = d_is64;
    while (lo < hi) {
        int mid = (lo + hi) >> 1;
        int v = is64 ? batch[2 * mid] : batch[mid];
        if (v < g) lo = mid + 1; else hi = mid;
    }
    d_gs[g] = lo;
}

__global__ void __launch_bounds__(128) k_pool() {
    int g = blockIdx.x;
    int f = threadIdx.x;
    int s0 = d_gs[g], s1 = d_gs[g + 1];
    float acc = 0.f;
    for (int n = s0; n < s1; n++) acc += d_h2[n * FH + f];
    float c = (float)max(s1 - s0, 1);
    d_gm[g * FH + f] = acc / c;
}

__global__ void __launch_bounds__(128) k_mlp(const float* __restrict__ Wm1,
                                             const float* __restrict__ bm1,
                                             const float* __restrict__ Wm2,
                                             const float* __restrict__ bm2,
                                             float* __restrict__ out) {
    __shared__ float sg[FH];
    __shared__ float red[4];
    int g = blockIdx.x;
    int j = threadIdx.x;
    sg[j] = d_gm[g * FH + j];
    __syncthreads();
    float acc = bm1[j];
#pragma unroll 8
    for (int k = 0; k < FH; k++) acc += sg[k] * Wm1[k * FH + j];
    float p = tanhf(acc) * Wm2[j];
#pragma unroll
    for (int o = 16; o > 0; o >>= 1)
        p += __shfl_xor_sync(0xFFFFFFFF, p, o);
    if ((j & 31) == 0) red[j >> 5] = p;
    __syncthreads();
    if (j == 0)
        out[g] = red[0] + red[1] + red[2] + red[3] + bm2[0];
}

// ---------------- launch ------------------------------------------------------
extern "C" void kernel_launch(void* const* d_in, const int* in_sizes, int n_in,
                              void* d_out, int out_size) {
    const float* x     = (const float*)d_in[0];
    const int*   ei    = (const int*)d_in[1];
    const int*   batch = (const int*)d_in[2];
    // weights are the last 8 arrays (robust to whether num_graphs scalar is present)
    int wb = n_in - 8;
    const float* W1  = (const float*)d_in[wb + 0];
    const float* b1  = (const float*)d_in[wb + 1];
    const float* W2  = (const float*)d_in[wb + 2];
    const float* b2  = (const float*)d_in[wb + 3];
    const float* Wm1 = (const float*)d_in[wb + 4];
    const float* bm1 = (const float*)d_in[wb + 5];
    const float* Wm2 = (const float*)d_in[wb + 6];
    const float* bm2 = (const float*)d_in[wb + 7];
    float* out = (float*)d_out;

    k_detect<<<1, 256>>>(ei);
    k_zero<<<(NN + 255) / 256, 256>>>();
    k_hist<<<(NE + 255) / 256, 256>>>(ei);
    k_scan1<<<NB, 1024>>>();
    k_scan2<<<1, 32>>>();
    k_scan3<<<NB, 1024>>>();
    k_dinv<<<(NN + 255) / 256, 256>>>();
    k_scatter<<<(NE + 255) / 256, 256>>>(ei);
    k_aggx<<<(NN + 127) / 128, 128>>>(x);
    k_lin1<<<(NN * FH + 255) / 256, 256>>>(W1, b1);
    k_agg128<<<(NN * 32 + 255) / 256, 256>>>();
    k_lin2<<<NN / 32, 256>>>(W2, b2);
    k_gstart<<<(NG + 128) / 128, 128>>>(batch);
    k_pool<<<NG, 128>>>();
    k_mlp<<<NG, 128>>>(Wm1, bm1, Wm2, bm2, out);
}

// round 2
// speedup vs baseline: 1.3819x; 1.3819x over previous
#include <cuda_runtime.h>
#include <cuda_fp16.h>
#include <math.h>

// Problem constants (fixed by the dataset)
#define NN 100000
#define NE 1600000
#define NG 1000
#define FIN 10
#define FH  128
#define NB  ((NN + 1023) / 1024)   // scan blocks = 98
#define NNPAD 100096               // NN rounded up to 128 (782 * 128)

// ---------------- scratch (device globals; no cudaMalloc allowed) -----------
__device__ int   d_cnt[NN];
__device__ int   d_cur[NN];
__device__ int   d_off[NN];
__device__ int   d_csr[NE];
__device__ float d_dinv[NN];
__device__ float d_aggx[NN * FIN];
__device__ __align__(16) __half d_h1h[NN * FH];       // layer-1 activations (fp16)
__device__ __align__(16) __half d_aggh[NNPAD * FH];   // 128-dim aggregation (fp16, padded)
__device__ __align__(16) __half d_w2t[FH * FH];       // W2 transposed [n][k] fp16
__device__ __align__(16) __half d_h2h[NN * FH];       // layer-2 activations (fp16)
__device__ float d_gm[NG * FH];
__device__ int   d_gs[NG + 1];
__device__ int   d_bsum[NB];
__device__ int   d_is64;

// ---------------- index dtype detection -------------------------------------
__global__ void k_detect(const int* __restrict__ ei) {
    __shared__ int nz;
    if (threadIdx.x == 0) nz = 0;
    __syncthreads();
    for (int i = threadIdx.x; i < 2048; i += blockDim.x)
        if ((i & 1) && ei[i] != 0) atomicOr(&nz, 1);
    __syncthreads();
    if (threadIdx.x == 0) d_is64 = (nz == 0) ? 1 : 0;
}

__device__ __forceinline__ int ld_src(const int* ei, int e) {
    return d_is64 ? ei[2 * e] : ei[e];
}
__device__ __forceinline__ int ld_dst(const int* ei, int e) {
    return d_is64 ? ei[2 * (NE + e)] : ei[NE + e];
}

// ---------------- CSR build --------------------------------------------------
__global__ void k_zero() {
    int i = blockIdx.x * blockDim.x + threadIdx.x;
    if (i < NN) { d_cnt[i] = 0; d_cur[i] = 0; }
}

__global__ void k_hist(const int* __restrict__ ei) {
    int e = blockIdx.x * blockDim.x + threadIdx.x;
    if (e < NE) atomicAdd(&d_cnt[ld_dst(ei, e)], 1);
}

__global__ void k_scan1() {
    __shared__ int s[1024];
    int i = blockIdx.x * 1024 + threadIdx.x;
    int v = (i < NN) ? d_cnt[i] : 0;
    s[threadIdx.x] = v;
    __syncthreads();
    for (int o = 1; o < 1024; o <<= 1) {
        int add = (threadIdx.x >= o) ? s[threadIdx.x - o] : 0;
        __syncthreads();
        s[threadIdx.x] += add;
        __syncthreads();
    }
    if (i < NN) d_off[i] = s[threadIdx.x] - v;
    if (threadIdx.x == 1023) d_bsum[blockIdx.x] = s[1023];
}

__global__ void k_scan2() {
    if (threadIdx.x == 0 && blockIdx.x == 0) {
        int run = 0;
        for (int b = 0; b < NB; b++) { int t = d_bsum[b]; d_bsum[b] = run; run += t; }
    }
}

__global__ void k_scan3() {
    int i = blockIdx.x * 1024 + threadIdx.x;
    if (i < NN) d_off[i] += d_bsum[blockIdx.x];
}

__global__ void k_dinv() {
    int i = blockIdx.x * blockDim.x + threadIdx.x;
    if (i < NN) d_dinv[i] = rsqrtf((float)(d_cnt[i] + 1));
}

__global__ void k_scatter(const int* __restrict__ ei) {
    int e = blockIdx.x * blockDim.x + threadIdx.x;
    if (e < NE) {
        int s = ld_src(ei, e);
        int d = ld_dst(ei, e);
        int pos = d_off[d] + atomicAdd(&d_cur[d], 1);
        d_csr[pos] = s;
    }
}

// ---------------- layer 1: aggregate x (10-dim), then linear ----------------
__global__ void k_aggx(const float* __restrict__ x) {
    int n = blockIdx.x * blockDim.x + threadIdx.x;
    if (n >= NN) return;
    float acc[FIN];
#pragma unroll
    for (int f = 0; f < FIN; f++) acc[f] = 0.f;
    int beg = d_off[n], len = d_cnt[n];
    for (int j = 0; j < len; j++) {
        int s = d_csr[beg + j];
        float w = d_dinv[s];
        const float* xr = x + s * FIN;
#pragma unroll
        for (int f = 0; f < FIN; f++) acc[f] += xr[f] * w;
    }
    float di = d_dinv[n];
    float d2 = di * di;
    const float* xn = x + n * FIN;
#pragma unroll
    for (int f = 0; f < FIN; f++)
        d_aggx[n * FIN + f] = di * acc[f] + d2 * xn[f];
}

__global__ void __launch_bounds__(256) k_lin1(const float* __restrict__ W1,
                                              const float* __restrict__ b1) {
    __shared__ float sW[FIN * FH];
    for (int i = threadIdx.x; i < FIN * FH; i += 256) sW[i] = W1[i];
    __syncthreads();
    int idx = blockIdx.x * 256 + threadIdx.x;
    int n = idx >> 7;
    int f = idx & 127;
    if (n >= NN) return;
    const float* a = d_aggx + n * FIN;
    float acc = b1[f];
#pragma unroll
    for (int k = 0; k < FIN; k++) acc += a[k] * sW[k * FH + f];
    d_h1h[n * FH + f] = __float2half(fmaxf(acc, 0.f));
}

// ---------------- layer 2: 128-dim aggregation (warp per node, fp16 gather) -
__global__ void __launch_bounds__(256) k_agg128() {
    int warp = (blockIdx.x * blockDim.x + threadIdx.x) >> 5;
    int lane = threadIdx.x & 31;
    if (warp >= NN) return;
    int n = warp;
    const uint2* H = (const uint2*)d_h1h;   // 32 uint2 (4 halves each) per row
    float a0 = 0.f, a1 = 0.f, a2 = 0.f, a3 = 0.f;
    int beg = d_off[n], len = d_cnt[n];
#pragma unroll 2
    for (int j = 0; j < len; j++) {
        int s = d_csr[beg + j];
        float w = d_dinv[s];
        uint2 v = H[s * 32 + lane];
        __half2 lo = *(__half2*)&v.x;
        __half2 hi = *(__half2*)&v.y;
        float2 flo = __half22float2(lo);
        float2 fhi = __half22float2(hi);
        a0 += flo.x * w; a1 += flo.y * w; a2 += fhi.x * w; a3 += fhi.y * w;
    }
    float di = d_dinv[n];
    float d2 = di * di;
    uint2 sv = H[n * 32 + lane];
    float2 slo = __half22float2(*(__half2*)&sv.x);
    float2 shi = __half22float2(*(__half2*)&sv.y);
    float r0 = di * a0 + d2 * slo.x;
    float r1 = di * a1 + d2 * slo.y;
    float r2 = di * a2 + d2 * shi.x;
    float r3 = di * a3 + d2 * shi.y;
    __half2 olo = __floats2half2_rn(r0, r1);
    __half2 ohi = __floats2half2_rn(r2, r3);
    uint2 o;
    o.x = *(unsigned int*)&olo;
    o.y = *(unsigned int*)&ohi;
    ((uint2*)d_aggh)[n * 32 + lane] = o;
}

__global__ void k_padagg() {
    int idx = blockIdx.x * blockDim.x + threadIdx.x;   // pad rows NN..NNPAD-1
    if (idx < (NNPAD - NN) * 32)
        ((uint2*)d_aggh)[NN * 32 + idx] = make_uint2(0u, 0u);
}

// ---------------- W2 -> fp16 transposed [n][k] -------------------------------
__global__ void k_w2t(const float* __restrict__ W2) {
    int i = blockIdx.x * blockDim.x + threadIdx.x;
    if (i < FH * FH) {
        int k = i >> 7, n = i & 127;
        d_w2t[n * FH + k] = __float2half(W2[i]);
    }
}

// ---------------- layer 2 linear via HMMA (m16n8k16) -------------------------
// Block: 256 threads = 8 warps; tile 128 rows x 128 cols; K chunked 2x64.
__global__ void __launch_bounds__(256) k_lin2t(const float* __restrict__ b2) {
    __shared__ __half sA[128][72];   // 64 K-halves + 8 pad
    __shared__ __half sB[128][72];   // W2T chunk: [n][k]
    __shared__ float  sBias[FH];

    const int tid  = threadIdx.x;
    const int lane = tid & 31;
    const int wid  = tid >> 5;           // 0..7 -> rows wid*16..wid*16+15
    const int grp  = lane >> 2;          // 0..7
    const int tig  = lane & 3;           // 0..3
    const int row0 = blockIdx.x * 128;

    if (tid < FH) sBias[tid] = b2[tid];

    float acc[16][4];
#pragma unroll
    for (int t = 0; t < 16; t++)
#pragma unroll
        for (int c = 0; c < 4; c++) acc[t][c] = 0.f;

    for (int kc = 0; kc < FH; kc += 64) {
        // load A chunk: 128 rows x 64 halves (8 uint4 per row)
        const uint4* Ag = (const uint4*)(d_aggh + (size_t)row0 * FH + kc);
#pragma unroll
        for (int i = 0; i < 4; i++) {
            int idx = tid + i * 256;
            int r = idx >> 3, q = idx & 7;
            // global row pitch = 128 halves = 16 uint4
            uint4 v = Ag[r * 16 + q];
            *(uint4*)&sA[r][q * 8] = v;
        }
        // load B chunk: W2T rows n=0..127, cols kc..kc+63
        const uint4* Bg = (const uint4*)(d_w2t + kc);
#pragma unroll
        for (int i = 0; i < 4; i++) {
            int idx = tid + i * 256;
            int r = idx >> 3, q = idx & 7;
            uint4 v = Bg[r * 16 + q];
            *(uint4*)&sB[r][q * 8] = v;
        }
        __syncthreads();

#pragma unroll
        for (int ks = 0; ks < 4; ks++) {
            int k0 = ks * 16;
            // A fragment via ldmatrix.x4
            unsigned a0, a1, a2, a3;
            {
                const __half* p = &sA[wid * 16 + (lane & 15)][k0 + ((lane >> 4) << 3)];
                unsigned addr = (unsigned)__cvta_generic_to_shared(p);
                asm volatile("ldmatrix.sync.aligned.m8n8.x4.shared.b16 {%0,%1,%2,%3}, [%4];"
                             : "=r"(a0), "=r"(a1), "=r"(a2), "=r"(a3) : "r"(addr));
            }
#pragma unroll
            for (int nt = 0; nt < 8; nt++) {   // each covers 16 n-cols (2 mma tiles)
                unsigned m0, m1, m2, m3;
                const __half* p = &sB[nt * 16 + (lane & 15)][k0 + ((lane >> 4) << 3)];
                unsigned addr = (unsigned)__cvta_generic_to_shared(p);
                asm volatile("ldmatrix.sync.aligned.m8n8.x4.shared.b16 {%0,%1,%2,%3}, [%4];"
                             : "=r"(m0), "=r"(m1), "=r"(m2), "=r"(m3) : "r"(addr));
                float* c0 = acc[nt * 2];
                float* c1 = acc[nt * 2 + 1];
                asm volatile("mma.sync.aligned.m16n8k16.row.col.f32.f16.f16.f32 "
                             "{%0,%1,%2,%3}, {%4,%5,%6,%7}, {%8,%9}, {%0,%1,%2,%3};"
                             : "+f"(c0[0]), "+f"(c0[1]), "+f"(c0[2]), "+f"(c0[3])
                             : "r"(a0), "r"(a1), "r"(a2), "r"(a3), "r"(m0), "r"(m2));
                asm volatile("mma.sync.aligned.m16n8k16.row.col.f32.f16.f16.f32 "
                             "{%0,%1,%2,%3}, {%4,%5,%6,%7}, {%8,%9}, {%0,%1,%2,%3};"
                             : "+f"(c1[0]), "+f"(c1[1]), "+f"(c1[2]), "+f"(c1[3])
                             : "r"(a0), "r"(a1), "r"(a2), "r"(a3), "r"(m1), "r"(m3));
            }
        }
        __syncthreads();
    }

    // epilogue: bias + relu -> fp16 store
    int rA = row0 + wid * 16 + grp;       // c0,c1 row
    int rB = rA + 8;                      // c2,c3 row
#pragma unroll
    for (int nt = 0; nt < 16; nt++) {
        int col = nt * 8 + tig * 2;
        float bx = sBias[col], by = sBias[col + 1];
        if (rA < NN) {
            __half2 h = __floats2half2_rn(fmaxf(acc[nt][0] + bx, 0.f),
                                          fmaxf(acc[nt][1] + by, 0.f));
            *(__half2*)&d_h2h[(size_t)rA * FH + col] = h;
        }
        if (rB < NN) {
            __half2 h = __floats2half2_rn(fmaxf(acc[nt][2] + bx, 0.f),
                                          fmaxf(acc[nt][3] + by, 0.f));
            *(__half2*)&d_h2h[(size_t)rB * FH + col] = h;
        }
    }
}

// ---------------- pooling + MLP ----------------------------------------------
__global__ void k_gstart(const int* __restrict__ batch) {
    int g = blockIdx.x * blockDim.x + threadIdx.x;
    if (g > NG) return;
    int lo = 0, hi = NN;
    int is64 = d_is64;
    while (lo < hi) {
        int mid = (lo + hi) >> 1;
        int v = is64 ? batch[2 * mid] : batch[mid];
        if (v < g) lo = mid + 1; else hi = mid;
    }
    d_gs[g] = lo;
}

__global__ void __launch_bounds__(128) k_pool() {
    int g = blockIdx.x;
    int f = threadIdx.x;
    int s0 = d_gs[g], s1 = d_gs[g + 1];
    float acc = 0.f;
    for (int n = s0; n < s1; n++) acc += __half2float(d_h2h[(size_t)n * FH + f]);
    float c = (float)max(s1 - s0, 1);
    d_gm[g * FH + f] = acc / c;
}

__global__ void __launch_bounds__(128) k_mlp(const float* __restrict__ Wm1,
                                             const float* __restrict__ bm1,
                                             const float* __restrict__ Wm2,
                                             const float* __restrict__ bm2,
                                             float* __restrict__ out) {
    __shared__ float sg[FH];
    __shared__ float red[4];
    int g = blockIdx.x;
    int j = threadIdx.x;
    sg[j] = d_gm[g * FH + j];
    __syncthreads();
    float acc = bm1[j];
#pragma unroll 8
    for (int k = 0; k < FH; k++) acc += sg[k] * Wm1[k * FH + j];
    float p = tanhf(acc) * Wm2[j];
#pragma unroll
    for (int o = 16; o > 0; o >>= 1)
        p += __shfl_xor_sync(0xFFFFFFFF, p, o);
    if ((j & 31) == 0) red[j >> 5] = p;
    __syncthreads();
    if (j == 0)
        out[g] = red[0] + red[1] + red[2] + red[3] + bm2[0];
}

// ---------------- launch ------------------------------------------------------
extern "C" void kernel_launch(void* const* d_in, const int* in_sizes, int n_in,
                              void* d_out, int out_size) {
    const float* x     = (const float*)d_in[0];
    const int*   ei    = (const int*)d_in[1];
    const int*   batch = (const int*)d_in[2];
    int wb = n_in - 8;
    const float* W1  = (const float*)d_in[wb + 0];
    const float* b1  = (const float*)d_in[wb + 1];
    const float* W2  = (const float*)d_in[wb + 2];
    const float* b2  = (const float*)d_in[wb + 3];
    const float* Wm1 = (const float*)d_in[wb + 4];
    const float* bm1 = (const float*)d_in[wb + 5];
    const float* Wm2 = (const float*)d_in[wb + 6];
    const float* bm2 = (const float*)d_in[wb + 7];
    float* out = (float*)d_out;

    k_detect<<<1, 256>>>(ei);
    k_zero<<<(NN + 255) / 256, 256>>>();
    k_hist<<<(NE + 255) / 256, 256>>>(ei);
    k_scan1<<<NB, 1024>>>();
    k_scan2<<<1, 32>>>();
    k_scan3<<<NB, 1024>>>();
    k_dinv<<<(NN + 255) / 256, 256>>>();
    k_scatter<<<(NE + 255) / 256, 256>>>(ei);
    k_w2t<<<(FH * FH + 255) / 256, 256>>>(W2);
    k_aggx<<<(NN + 127) / 128, 128>>>(x);
    k_lin1<<<(NN * FH + 255) / 256, 256>>>(W1, b1);
    k_agg128<<<(NN * 32 + 255) / 256, 256>>>();
    k_padagg<<<3, 1024>>>();
    k_lin2t<<<NNPAD / 128, 256>>>(b2);
    k_gstart<<<(NG + 128) / 128, 128>>>(batch);
    k_pool<<<NG, 128>>>();
    k_mlp<<<NG, 128>>>(Wm1, bm1, Wm2, bm2, out);
}

// round 3
// speedup vs baseline: 1.5478x; 1.1201x over previous
#include <cuda_runtime.h>
#include <cuda_fp16.h>
#include <math.h>

// Problem constants (fixed by the dataset)
#define NN 100000
#define NE 1600000
#define NG 1000
#define FIN 10
#define FH  128
#define NB  ((NN + 1023) / 1024)   // scan blocks = 98
#define NBLK 782                   // ceil(NN/128)

// ---------------- scratch (device globals; no cudaMalloc allowed) -----------
__device__ int   d_cnt[NN];
__device__ int   d_cur[NN];
__device__ int   d_off[NN];
__device__ int   d_csr[NE];
__device__ float d_dinv[NN];
__device__ __align__(16) __half d_xh[NN * 16];        // x padded to 16 halves/row
__device__ __align__(16) __half d_h1h[NN * FH];       // layer-1 activations (fp16)
__device__ __align__(16) __half d_w2t[FH * FH];       // W2 transposed [n][k] fp16
__device__ __align__(16) __half d_h2h[NN * FH];       // layer-2 activations (fp16)
__device__ int   d_bsum[NB];
__device__ int   d_is64;

// ---------------- detect dtype + zero counters --------------------------------
__global__ void k_detect(const int* __restrict__ ei) {
    int i = blockIdx.x * blockDim.x + threadIdx.x;
    if (i < NN) { d_cnt[i] = 0; d_cur[i] = 0; }
    if (blockIdx.x == 0) {
        __shared__ int nz;
        if (threadIdx.x == 0) nz = 0;
        __syncthreads();
        // int64 little-endian with values < 2^31 => all odd 32-bit words zero
        for (int j = threadIdx.x; j < 2048; j += blockDim.x)
            if ((j & 1) && ei[j] != 0) atomicOr(&nz, 1);
        __syncthreads();
        if (threadIdx.x == 0) d_is64 = (nz == 0) ? 1 : 0;
    }
}

// ---------------- CSR build --------------------------------------------------
__global__ void k_hist(const int* __restrict__ ei) {
    int i = blockIdx.x * blockDim.x + threadIdx.x;   // handles edges 2i, 2i+1
    if (i >= NE / 2) return;
    if (d_is64) {
        int4 d4 = ((const int4*)(ei + 2 * NE))[i];
        atomicAdd(&d_cnt[d4.x], 1);
        atomicAdd(&d_cnt[d4.z], 1);
    } else {
        int2 d2 = ((const int2*)(ei + NE))[i];
        atomicAdd(&d_cnt[d2.x], 1);
        atomicAdd(&d_cnt[d2.y], 1);
    }
}

__global__ void k_scan1() {
    __shared__ int s[1024];
    int i = blockIdx.x * 1024 + threadIdx.x;
    int v = (i < NN) ? d_cnt[i] : 0;
    s[threadIdx.x] = v;
    __syncthreads();
    for (int o = 1; o < 1024; o <<= 1) {
        int add = (threadIdx.x >= o) ? s[threadIdx.x - o] : 0;
        __syncthreads();
        s[threadIdx.x] += add;
        __syncthreads();
    }
    if (i < NN) d_off[i] = s[threadIdx.x] - v;
    if (threadIdx.x == 1023) d_bsum[blockIdx.x] = s[1023];
}

__global__ void k_scan2() {   // parallel exclusive scan of 98 block sums
    int t = threadIdx.x;
    int lane = t & 31, w = t >> 5;
    int v = (t < NB) ? d_bsum[t] : 0;
    int s = v;
#pragma unroll
    for (int o = 1; o < 32; o <<= 1) {
        int u = __shfl_up_sync(0xFFFFFFFF, s, o);
        if (lane >= o) s += u;
    }
    __shared__ int ws[4];
    if (lane == 31) ws[w] = s;
    __syncthreads();
    int add = 0;
    for (int i = 0; i < w; i++) add += ws[i];
    s += add;
    if (t < NB) d_bsum[t] = s - v;   // exclusive
}

__global__ void k_scan3() {
    int i = blockIdx.x * 1024 + threadIdx.x;
    if (i < NN) {
        d_off[i] += d_bsum[blockIdx.x];
        d_dinv[i] = rsqrtf((float)(d_cnt[i] + 1));
    }
}

__global__ void k_scatter(const int* __restrict__ ei) {
    int i = blockIdx.x * blockDim.x + threadIdx.x;
    if (i >= NE / 2) return;
    int s0, s1, dd0, dd1;
    if (d_is64) {
        int4 s4 = ((const int4*)ei)[i];
        int4 d4 = ((const int4*)(ei + 2 * NE))[i];
        s0 = s4.x; s1 = s4.z; dd0 = d4.x; dd1 = d4.z;
    } else {
        int2 s2 = ((const int2*)ei)[i];
        int2 d2 = ((const int2*)(ei + NE))[i];
        s0 = s2.x; s1 = s2.y; dd0 = d2.x; dd1 = d2.y;
    }
    int p0 = d_off[dd0] + atomicAdd(&d_cur[dd0], 1);
    d_csr[p0] = s0;
    int p1 = d_off[dd1] + atomicAdd(&d_cur[dd1], 1);
    d_csr[p1] = s1;
}

// ---------------- prep: x -> fp16 padded, W2 -> fp16 transposed --------------
__global__ void k_prep(const float* __restrict__ x, const float* __restrict__ W2) {
    int idx = blockIdx.x * blockDim.x + threadIdx.x;
    if (idx < NN * 16) {
        int n = idx >> 4, c = idx & 15;
        d_xh[idx] = (c < FIN) ? __float2half(x[n * FIN + c]) : __half(0);
    }
    if (idx < FH * FH) {
        int k = idx >> 7, n = idx & 127;
        d_w2t[n * FH + k] = __float2half(W2[idx]);
    }
}

// ---------------- layer 1 fused: 10-dim aggregate + linear + relu ------------
__global__ void __launch_bounds__(128) k_l1(const float* __restrict__ W1,
                                            const float* __restrict__ b1) {
    __shared__ float sax[128][FIN];
    const int tid = threadIdx.x;
    const int row0 = blockIdx.x * 128;
    // phase 1: thread-per-node 10-dim aggregation from padded fp16 x
    {
        int n = row0 + tid;
        float acc[FIN];
#pragma unroll
        for (int f = 0; f < FIN; f++) acc[f] = 0.f;
        if (n < NN) {
            int beg = d_off[n], len = d_cnt[n];
            const uint4* X4 = (const uint4*)d_xh;
            const unsigned* X1 = (const unsigned*)d_xh;
            for (int j = 0; j < len; j++) {
                int s = d_csr[beg + j];
                float w = d_dinv[s];
                uint4 v = X4[s * 2];
                unsigned v4 = X1[s * 8 + 4];
                float2 f0 = __half22float2(*(__half2*)&v.x);
                float2 f1 = __half22float2(*(__half2*)&v.y);
                float2 f2 = __half22float2(*(__half2*)&v.z);
                float2 f3 = __half22float2(*(__half2*)&v.w);
                float2 f4 = __half22float2(*(__half2*)&v4);
                acc[0] += f0.x * w; acc[1] += f0.y * w;
                acc[2] += f1.x * w; acc[3] += f1.y * w;
                acc[4] += f2.x * w; acc[5] += f2.y * w;
                acc[6] += f3.x * w; acc[7] += f3.y * w;
                acc[8] += f4.x * w; acc[9] += f4.y * w;
            }
            float di = d_dinv[n];
            float d2 = di * di;
            uint4 v = X4[n * 2];
            unsigned v4 = X1[n * 8 + 4];
            float2 f0 = __half22float2(*(__half2*)&v.x);
            float2 f1 = __half22float2(*(__half2*)&v.y);
            float2 f2 = __half22float2(*(__half2*)&v.z);
            float2 f3 = __half22float2(*(__half2*)&v.w);
            float2 f4 = __half22float2(*(__half2*)&v4);
            acc[0] = di * acc[0] + d2 * f0.x; acc[1] = di * acc[1] + d2 * f0.y;
            acc[2] = di * acc[2] + d2 * f1.x; acc[3] = di * acc[3] + d2 * f1.y;
            acc[4] = di * acc[4] + d2 * f2.x; acc[5] = di * acc[5] + d2 * f2.y;
            acc[6] = di * acc[6] + d2 * f3.x; acc[7] = di * acc[7] + d2 * f3.y;
            acc[8] = di * acc[8] + d2 * f4.x; acc[9] = di * acc[9] + d2 * f4.y;
        }
#pragma unroll
        for (int f = 0; f < FIN; f++) sax[tid][f] = acc[f];
    }
    __syncthreads();
    // phase 2: thread-per-feature linear; coalesced fp16 writes
    float w1c[FIN];
#pragma unroll
    for (int k = 0; k < FIN; k++) w1c[k] = W1[k * FH + tid];
    float bb = b1[tid];
    int nmax = min(128, NN - row0);
    for (int n = 0; n < nmax; n++) {
        float acc = bb;
#pragma unroll
        for (int k = 0; k < FIN; k++) acc += sax[n][k] * w1c[k];
        d_h1h[(size_t)(row0 + n) * FH + tid] = __float2half(fmaxf(acc, 0.f));
    }
}

// ---------------- layer 2 fused: 128-dim aggregate + HMMA linear + relu ------
// Block: 256 threads (8 warps). 128 nodes/block. smem: sA[128][136], sW[128][136].
#define SASTRIDE 136
__global__ void __launch_bounds__(256) k_l2(const float* __restrict__ b2) {
    extern __shared__ __half smemBuf[];
    __half* sA = smemBuf;                       // 128 x 136
    __half* sW = smemBuf + 128 * SASTRIDE;      // 128 x 136 (W2T rows n, cols k)
    float*  sBias = (float*)(smemBuf + 2 * 128 * SASTRIDE);

    const int tid  = threadIdx.x;
    const int lane = tid & 31;
    const int wid  = tid >> 5;
    const int row0 = blockIdx.x * 128;

    // load W2T into smem (16384 halves, 8 per thread-iter)
#pragma unroll
    for (int i = 0; i < 8; i++) {
        int idx = tid + i * 256;              // 0..2047, 8 halves each
        int r = idx >> 4, q = idx & 15;
        uint4 v = ((const uint4*)d_w2t)[idx];
        *(uint4*)&sW[r * SASTRIDE + q * 8] = v;
    }
    if (tid < FH) sBias[tid] = b2[tid];

    // aggregation phase: warp per node, 16 nodes per warp
    const uint2* H = (const uint2*)d_h1h;
    for (int i = 0; i < 16; i++) {
        int nl = wid * 16 + i;
        int n = row0 + nl;
        float a0 = 0.f, a1 = 0.f, a2 = 0.f, a3 = 0.f;
        if (n < NN) {
            int beg = d_off[n], len = d_cnt[n];
#pragma unroll 4
            for (int j = 0; j < len; j++) {
                int s = d_csr[beg + j];
                float w = d_dinv[s];
                uint2 v = H[s * 32 + lane];
                float2 flo = __half22float2(*(__half2*)&v.x);
                float2 fhi = __half22float2(*(__half2*)&v.y);
                a0 += flo.x * w; a1 += flo.y * w; a2 += fhi.x * w; a3 += fhi.y * w;
            }
            float di = d_dinv[n];
            float d2 = di * di;
            uint2 sv = H[n * 32 + lane];
            float2 slo = __half22float2(*(__half2*)&sv.x);
            float2 shi = __half22float2(*(__half2*)&sv.y);
            a0 = di * a0 + d2 * slo.x;
            a1 = di * a1 + d2 * slo.y;
            a2 = di * a2 + d2 * shi.x;
            a3 = di * a3 + d2 * shi.y;
        }
        __half2 olo = __floats2half2_rn(a0, a1);
        __half2 ohi = __floats2half2_rn(a2, a3);
        uint2 o;
        o.x = *(unsigned*)&olo;
        o.y = *(unsigned*)&ohi;
        *(uint2*)&sA[nl * SASTRIDE + lane * 4] = o;
    }
    __syncthreads();

    // HMMA phase: 8 k-steps of m16n8k16 over full K=128
    float acc[16][4];
#pragma unroll
    for (int t = 0; t < 16; t++)
#pragma unroll
        for (int c = 0; c < 4; c++) acc[t][c] = 0.f;

#pragma unroll
    for (int ks = 0; ks < 8; ks++) {
        int k0 = ks * 16;
        unsigned a0, a1, a2, a3;
        {
            const __half* p = &sA[(wid * 16 + (lane & 15)) * SASTRIDE + k0 + ((lane >> 4) << 3)];
            unsigned addr = (unsigned)__cvta_generic_to_shared(p);
            asm volatile("ldmatrix.sync.aligned.m8n8.x4.shared.b16 {%0,%1,%2,%3}, [%4];"
                         : "=r"(a0), "=r"(a1), "=r"(a2), "=r"(a3) : "r"(addr));
        }
#pragma unroll
        for (int nt = 0; nt < 8; nt++) {
            unsigned m0, m1, m2, m3;
            const __half* p = &sW[(nt * 16 + (lane & 15)) * SASTRIDE + k0 + ((lane >> 4) << 3)];
            unsigned addr = (unsigned)__cvta_generic_to_shared(p);
            asm volatile("ldmatrix.sync.aligned.m8n8.x4.shared.b16 {%0,%1,%2,%3}, [%4];"
                         : "=r"(m0), "=r"(m1), "=r"(m2), "=r"(m3) : "r"(addr));
            float* c0 = acc[nt * 2];
            float* c1 = acc[nt * 2 + 1];
            asm volatile("mma.sync.aligned.m16n8k16.row.col.f32.f16.f16.f32 "
                         "{%0,%1,%2,%3}, {%4,%5,%6,%7}, {%8,%9}, {%0,%1,%2,%3};"
                         : "+f"(c0[0]), "+f"(c0[1]), "+f"(c0[2]), "+f"(c0[3])
                         : "r"(a0), "r"(a1), "r"(a2), "r"(a3), "r"(m0), "r"(m2));
            asm volatile("mma.sync.aligned.m16n8k16.row.col.f32.f16.f16.f32 "
                         "{%0,%1,%2,%3}, {%4,%5,%6,%7}, {%8,%9}, {%0,%1,%2,%3};"
                         : "+f"(c1[0]), "+f"(c1[1]), "+f"(c1[2]), "+f"(c1[3])
                         : "r"(a0), "r"(a1), "r"(a2), "r"(a3), "r"(m1), "r"(m3));
        }
    }

    // epilogue: bias + relu -> fp16 store
    const int grp = lane >> 2;
    const int tig = lane & 3;
    int rA = row0 + wid * 16 + grp;
    int rB = rA + 8;
#pragma unroll
    for (int nt = 0; nt < 16; nt++) {
        int col = nt * 8 + tig * 2;
        float bx = sBias[col], by = sBias[col + 1];
        if (rA < NN) {
            __half2 h = __floats2half2_rn(fmaxf(acc[nt][0] + bx, 0.f),
                                          fmaxf(acc[nt][1] + by, 0.f));
            *(__half2*)&d_h2h[(size_t)rA * FH + col] = h;
        }
        if (rB < NN) {
            __half2 h = __floats2half2_rn(fmaxf(acc[nt][2] + bx, 0.f),
                                          fmaxf(acc[nt][3] + by, 0.f));
            *(__half2*)&d_h2h[(size_t)rB * FH + col] = h;
        }
    }
}

// ---------------- pooling + value MLP fused (block per graph) ----------------
__global__ void __launch_bounds__(128) k_poolmlp(const int* __restrict__ batch,
                                                 const float* __restrict__ Wm1,
                                                 const float* __restrict__ bm1,
                                                 const float* __restrict__ Wm2,
                                                 const float* __restrict__ bm2,
                                                 float* __restrict__ out) {
    __shared__ float sg[FH];
    __shared__ float red[4];
    const int g = blockIdx.x;
    const int j = threadIdx.x;
    const int is64 = d_is64;
    // binary search graph boundaries (redundant per thread; L2-hot)
    int s0, s1;
    {
        int lo = 0, hi = NN;
        while (lo < hi) {
            int mid = (lo + hi) >> 1;
            int v = is64 ? batch[2 * mid] : batch[mid];
            if (v < g) lo = mid + 1; else hi = mid;
        }
        s0 = lo;
        lo = 0; hi = NN;
        while (lo < hi) {
            int mid = (lo + hi) >> 1;
            int v = is64 ? batch[2 * mid] : batch[mid];
            if (v < g + 1) lo = mid + 1; else hi = mid;
        }
        s1 = lo;
    }
    float acc = 0.f;
    for (int n = s0; n < s1; n++)
        acc += __half2float(d_h2h[(size_t)n * FH + j]);
    sg[j] = acc / (float)max(s1 - s0, 1);
    __syncthreads();
    float a = bm1[j];
#pragma unroll 8
    for (int k = 0; k < FH; k++) a += sg[k] * Wm1[k * FH + j];
    float p = tanhf(a) * Wm2[j];
#pragma unroll
    for (int o = 16; o > 0; o >>= 1)
        p += __shfl_xor_sync(0xFFFFFFFF, p, o);
    if ((j & 31) == 0) red[j >> 5] = p;
    __syncthreads();
    if (j == 0)
        out[g] = red[0] + red[1] + red[2] + red[3] + bm2[0];
}

// ---------------- launch ------------------------------------------------------
extern "C" void kernel_launch(void* const* d_in, const int* in_sizes, int n_in,
                              void* d_out, int out_size) {
    const float* x     = (const float*)d_in[0];
    const int*   ei    = (const int*)d_in[1];
    const int*   batch = (const int*)d_in[2];
    int wb = n_in - 8;
    const float* W1  = (const float*)d_in[wb + 0];
    const float* b1  = (const float*)d_in[wb + 1];
    const float* W2  = (const float*)d_in[wb + 2];
    const float* b2  = (const float*)d_in[wb + 3];
    const float* Wm1 = (const float*)d_in[wb + 4];
    const float* bm1 = (const float*)d_in[wb + 5];
    const float* Wm2 = (const float*)d_in[wb + 6];
    const float* bm2 = (const float*)d_in[wb + 7];
    float* out = (float*)d_out;

    const int smem_l2 = (2 * 128 * SASTRIDE) * 2 + FH * 4;   // 70144 bytes
    cudaFuncSetAttribute(k_l2, cudaFuncAttributeMaxDynamicSharedMemorySize, smem_l2);

    k_detect<<<(NN + 255) / 256, 256>>>(ei);
    k_hist<<<(NE / 2 + 255) / 256, 256>>>(ei);
    k_scan1<<<NB, 1024>>>();
    k_scan2<<<1, 128>>>();
    k_scan3<<<NB, 1024>>>();
    k_scatter<<<(NE / 2 + 255) / 256, 256>>>(ei);
    k_prep<<<(NN * 16 + 255) / 256, 256>>>(x, W2);
    k_l1<<<NBLK, 128>>>(W1, b1);
    k_l2<<<NBLK, 256, smem_l2>>>(b2);
    k_poolmlp<<<NG, 128>>>(batch, Wm1, bm1, Wm2, bm2, out);
}

// round 4
// speedup vs baseline: 1.6306x; 1.0535x over previous
#include <cuda_runtime.h>
#include <cuda_fp16.h>
#include <math.h>

// Problem constants (fixed by the dataset)
#define NN 100000
#define NE 1600000
#define NG 1000
#define FIN 10
#define FH  128
#define NB  ((NN + 1023) / 1024)   // scan blocks = 98
#define NBLK 782                   // ceil(NN/128)

// ---------------- scratch (device globals; no cudaMalloc allowed) -----------
__device__ int   d_cnt[NN];
__device__ int   d_off[NN];
__device__ int   d_rank[NE];          // edge rank within its dst bucket
__device__ int   d_csr[NE];
__device__ float d_dinv[NN];
__device__ __align__(16) __half d_xh[NN * 16];   // dinv-scaled x, padded 16/row
__device__ __align__(16) __half d_h1h[NN * FH];  // dinv-scaled layer-1 act (fp16)
__device__ __align__(16) __half d_w2t[FH * FH];  // W2 transposed [n][k] fp16
__device__ __align__(16) __half d_h2h[NN * FH];  // layer-2 activations (fp16)
__device__ unsigned long long d_state[NB];       // lookback scan state
__device__ int   d_is64;

// ---------------- init: zero cnt/state, detect dtype, convert W2 -------------
__global__ void k_init(const int* __restrict__ ei, const float* __restrict__ W2) {
    int i = blockIdx.x * blockDim.x + threadIdx.x;
    if (i < NN) d_cnt[i] = 0;
    if (i < NB) d_state[i] = 0ULL;
    if (i < FH * FH) {
        int k = i >> 7, n = i & 127;
        d_w2t[n * FH + k] = __float2half(W2[i]);
    }
    if (blockIdx.x == 0) {
        __shared__ int nz;
        if (threadIdx.x == 0) nz = 0;
        __syncthreads();
        // int64 little-endian with values < 2^31 => all odd 32-bit words zero
        for (int j = threadIdx.x; j < 2048; j += blockDim.x)
            if ((j & 1) && ei[j] != 0) atomicOr(&nz, 1);
        __syncthreads();
        if (threadIdx.x == 0) d_is64 = (nz == 0) ? 1 : 0;
    }
}

// ---------------- histogram + rank assignment --------------------------------
__global__ void k_hist(const int* __restrict__ ei) {
    int i = blockIdx.x * blockDim.x + threadIdx.x;   // handles edges 2i, 2i+1
    if (i >= NE / 2) return;
    int dd0, dd1;
    if (d_is64) {
        int4 d4 = ((const int4*)(ei + 2 * NE))[i];
        dd0 = d4.x; dd1 = d4.z;
    } else {
        int2 d2 = ((const int2*)(ei + NE))[i];
        dd0 = d2.x; dd1 = d2.y;
    }
    int r0 = atomicAdd(&d_cnt[dd0], 1);
    int r1 = atomicAdd(&d_cnt[dd1], 1);
    ((int2*)d_rank)[i] = make_int2(r0, r1);
}

// ---------------- single-pass scan (decoupled lookback) + dinv + x scale -----
__global__ void __launch_bounds__(1024) k_scan(const float* __restrict__ x) {
    __shared__ int s[1024];
    __shared__ int exc;
    const int tid = threadIdx.x;
    const int bid = blockIdx.x;
    const int i = bid * 1024 + tid;
    int v = (i < NN) ? d_cnt[i] : 0;
    s[tid] = v;
    __syncthreads();
    for (int o = 1; o < 1024; o <<= 1) {
        int add = (tid >= o) ? s[tid - o] : 0;
        __syncthreads();
        s[tid] += add;
        __syncthreads();
    }
    if (tid == 0) {
        int total = s[1023];
        if (bid == 0) {
            atomicExch(&d_state[0], (2ULL << 32) | (unsigned)total);
            exc = 0;
        } else {
            atomicExch(&d_state[bid], (1ULL << 32) | (unsigned)total);
            int run = 0;
            for (int p = bid - 1; p >= 0; p--) {
                unsigned long long q;
                do { q = atomicAdd(&d_state[p], 0ULL); } while ((q >> 32) == 0ULL);
                run += (int)(unsigned)q;
                if ((q >> 32) == 2ULL) break;
            }
            atomicExch(&d_state[bid], (2ULL << 32) | (unsigned)(run + total));
            exc = run;
        }
    }
    __syncthreads();
    if (i < NN) {
        d_off[i] = exc + s[tid] - v;
        float di = rsqrtf((float)(v + 1));
        d_dinv[i] = di;
        // dinv-scaled fp16 x row, padded to 16 halves
        const float* xr = x + (size_t)i * FIN;
        __half2 h[8];
#pragma unroll
        for (int c = 0; c < 5; c++)
            h[c] = __floats2half2_rn(xr[2 * c] * di, xr[2 * c + 1] * di);
#pragma unroll
        for (int c = 5; c < 8; c++) h[c] = __floats2half2_rn(0.f, 0.f);
        uint4 v0 = make_uint4(*(unsigned*)&h[0], *(unsigned*)&h[1],
                              *(unsigned*)&h[2], *(unsigned*)&h[3]);
        uint4 v1 = make_uint4(*(unsigned*)&h[4], *(unsigned*)&h[5],
                              *(unsigned*)&h[6], *(unsigned*)&h[7]);
        ((uint4*)d_xh)[i * 2]     = v0;
        ((uint4*)d_xh)[i * 2 + 1] = v1;
    }
}

// ---------------- scatter (atomic-free: rank precomputed) --------------------
__global__ void k_scatter(const int* __restrict__ ei) {
    int i = blockIdx.x * blockDim.x + threadIdx.x;
    if (i >= NE / 2) return;
    int s0, s1, dd0, dd1;
    if (d_is64) {
        int4 s4 = ((const int4*)ei)[i];
        int4 d4 = ((const int4*)(ei + 2 * NE))[i];
        s0 = s4.x; s1 = s4.z; dd0 = d4.x; dd1 = d4.z;
    } else {
        int2 s2 = ((const int2*)ei)[i];
        int2 d2 = ((const int2*)(ei + NE))[i];
        s0 = s2.x; s1 = s2.y; dd0 = d2.x; dd1 = d2.y;
    }
    int2 r = ((const int2*)d_rank)[i];
    d_csr[d_off[dd0] + r.x] = s0;
    d_csr[d_off[dd1] + r.y] = s1;
}

// ---------------- layer 1 fused: aggregate (pre-scaled x) + linear + relu ----
__global__ void __launch_bounds__(128) k_l1(const float* __restrict__ W1,
                                            const float* __restrict__ b1) {
    __shared__ float sax[128][FIN];
    __shared__ float sdinv[128];
    const int tid = threadIdx.x;
    const int row0 = blockIdx.x * 128;
    {
        int n = row0 + tid;
        float acc[FIN];
#pragma unroll
        for (int f = 0; f < FIN; f++) acc[f] = 0.f;
        float di = 0.f;
        if (n < NN) {
            di = d_dinv[n];
            int beg = d_off[n], len = d_cnt[n];
            const uint4* X4 = (const uint4*)d_xh;
            const unsigned* X1 = (const unsigned*)d_xh;
            for (int j = 0; j <= len; j++) {         // <= : last iter adds self row
                int s = (j < len) ? d_csr[beg + j] : n;
                uint4 v = X4[s * 2];
                unsigned v4 = X1[s * 8 + 4];
                float2 f0 = __half22float2(*(__half2*)&v.x);
                float2 f1 = __half22float2(*(__half2*)&v.y);
                float2 f2 = __half22float2(*(__half2*)&v.z);
                float2 f3 = __half22float2(*(__half2*)&v.w);
                float2 f4 = __half22float2(*(__half2*)&v4);
                acc[0] += f0.x; acc[1] += f0.y;
                acc[2] += f1.x; acc[3] += f1.y;
                acc[4] += f2.x; acc[5] += f2.y;
                acc[6] += f3.x; acc[7] += f3.y;
                acc[8] += f4.x; acc[9] += f4.y;
            }
        }
        sdinv[tid] = di;
#pragma unroll
        for (int f = 0; f < FIN; f++) sax[tid][f] = acc[f] * di;
    }
    __syncthreads();
    // phase 2: thread-per-feature linear; write dinv-scaled fp16 h1'
    float w1c[FIN];
#pragma unroll
    for (int k = 0; k < FIN; k++) w1c[k] = W1[k * FH + tid];
    float bb = b1[tid];
    int nmax = min(128, NN - row0);
    for (int n = 0; n < nmax; n++) {
        float acc = bb;
#pragma unroll
        for (int k = 0; k < FIN; k++) acc += sax[n][k] * w1c[k];
        float h = fmaxf(acc, 0.f) * sdinv[n];
        d_h1h[(size_t)(row0 + n) * FH + tid] = __float2half(h);
    }
}

// ---------------- layer 2 fused: aggregate (pre-scaled h1') + HMMA + relu ----
#define SASTRIDE 136
__global__ void __launch_bounds__(256) k_l2(const float* __restrict__ b2) {
    extern __shared__ __half smemBuf[];
    __half* sA = smemBuf;                       // 128 x 136
    __half* sW = smemBuf + 128 * SASTRIDE;      // 128 x 136 (W2T rows n, cols k)
    float*  sBias = (float*)(smemBuf + 2 * 128 * SASTRIDE);

    const int tid  = threadIdx.x;
    const int lane = tid & 31;
    const int wid  = tid >> 5;
    const int row0 = blockIdx.x * 128;

#pragma unroll
    for (int i = 0; i < 8; i++) {
        int idx = tid + i * 256;
        int r = idx >> 4, q = idx & 15;
        uint4 v = ((const uint4*)d_w2t)[idx];
        *(uint4*)&sW[r * SASTRIDE + q * 8] = v;
    }
    if (tid < FH) sBias[tid] = b2[tid];

    // aggregation: warp per node, 16 nodes per warp; inner loop load-only
    const uint2* H = (const uint2*)d_h1h;
    for (int i = 0; i < 16; i++) {
        int nl = wid * 16 + i;
        int n = row0 + nl;
        float a0 = 0.f, a1 = 0.f, a2 = 0.f, a3 = 0.f;
        if (n < NN) {
            int beg = d_off[n], len = d_cnt[n];
#pragma unroll 4
            for (int j = 0; j <= len; j++) {         // last iter = self row
                int s = (j < len) ? d_csr[beg + j] : n;
                uint2 v = H[s * 32 + lane];
                float2 flo = __half22float2(*(__half2*)&v.x);
                float2 fhi = __half22float2(*(__half2*)&v.y);
                a0 += flo.x; a1 += flo.y; a2 += fhi.x; a3 += fhi.y;
            }
            float di = d_dinv[n];
            a0 *= di; a1 *= di; a2 *= di; a3 *= di;
        }
        __half2 olo = __floats2half2_rn(a0, a1);
        __half2 ohi = __floats2half2_rn(a2, a3);
        uint2 o;
        o.x = *(unsigned*)&olo;
        o.y = *(unsigned*)&ohi;
        *(uint2*)&sA[nl * SASTRIDE + lane * 4] = o;
    }
    __syncthreads();

    // HMMA: 8 k-steps of m16n8k16 over K=128
    float acc[16][4];
#pragma unroll
    for (int t = 0; t < 16; t++)
#pragma unroll
        for (int c = 0; c < 4; c++) acc[t][c] = 0.f;

#pragma unroll
    for (int ks = 0; ks < 8; ks++) {
        int k0 = ks * 16;
        unsigned a0, a1, a2, a3;
        {
            const __half* p = &sA[(wid * 16 + (lane & 15)) * SASTRIDE + k0 + ((lane >> 4) << 3)];
            unsigned addr = (unsigned)__cvta_generic_to_shared(p);
            asm volatile("ldmatrix.sync.aligned.m8n8.x4.shared.b16 {%0,%1,%2,%3}, [%4];"
                         : "=r"(a0), "=r"(a1), "=r"(a2), "=r"(a3) : "r"(addr));
        }
#pragma unroll
        for (int nt = 0; nt < 8; nt++) {
            unsigned m0, m1, m2, m3;
            const __half* p = &sW[(nt * 16 + (lane & 15)) * SASTRIDE + k0 + ((lane >> 4) << 3)];
            unsigned addr = (unsigned)__cvta_generic_to_shared(p);
            asm volatile("ldmatrix.sync.aligned.m8n8.x4.shared.b16 {%0,%1,%2,%3}, [%4];"
                         : "=r"(m0), "=r"(m1), "=r"(m2), "=r"(m3) : "r"(addr));
            float* c0 = acc[nt * 2];
            float* c1 = acc[nt * 2 + 1];
            asm volatile("mma.sync.aligned.m16n8k16.row.col.f32.f16.f16.f32 "
                         "{%0,%1,%2,%3}, {%4,%5,%6,%7}, {%8,%9}, {%0,%1,%2,%3};"
                         : "+f"(c0[0]), "+f"(c0[1]), "+f"(c0[2]), "+f"(c0[3])
                         : "r"(a0), "r"(a1), "r"(a2), "r"(a3), "r"(m0), "r"(m2));
            asm volatile("mma.sync.aligned.m16n8k16.row.col.f32.f16.f16.f32 "
                         "{%0,%1,%2,%3}, {%4,%5,%6,%7}, {%8,%9}, {%0,%1,%2,%3};"
                         : "+f"(c1[0]), "+f"(c1[1]), "+f"(c1[2]), "+f"(c1[3])
                         : "r"(a0), "r"(a1), "r"(a2), "r"(a3), "r"(m1), "r"(m3));
        }
    }

    // epilogue: bias + relu -> fp16 store
    const int grp = lane >> 2;
    const int tig = lane & 3;
    int rA = row0 + wid * 16 + grp;
    int rB = rA + 8;
#pragma unroll
    for (int nt = 0; nt < 16; nt++) {
        int col = nt * 8 + tig * 2;
        float bx = sBias[col], by = sBias[col + 1];
        if (rA < NN) {
            __half2 h = __floats2half2_rn(fmaxf(acc[nt][0] + bx, 0.f),
                                          fmaxf(acc[nt][1] + by, 0.f));
            *(__half2*)&d_h2h[(size_t)rA * FH + col] = h;
        }
        if (rB < NN) {
            __half2 h = __floats2half2_rn(fmaxf(acc[nt][2] + bx, 0.f),
                                          fmaxf(acc[nt][3] + by, 0.f));
            *(__half2*)&d_h2h[(size_t)rB * FH + col] = h;
        }
    }
}

// ---------------- pooling + value MLP fused (block per graph) ----------------
__global__ void __launch_bounds__(128) k_poolmlp(const int* __restrict__ batch,
                                                 const float* __restrict__ Wm1,
                                                 const float* __restrict__ bm1,
                                                 const float* __restrict__ Wm2,
                                                 const float* __restrict__ bm2,
                                                 float* __restrict__ out) {
    __shared__ float sg[FH];
    __shared__ float red[4];
    const int g = blockIdx.x;
    const int j = threadIdx.x;
    const int is64 = d_is64;
    int s0, s1;
    {
        int lo = 0, hi = NN;
        while (lo < hi) {
            int mid = (lo + hi) >> 1;
            int v = is64 ? batch[2 * mid] : batch[mid];
            if (v < g) lo = mid + 1; else hi = mid;
        }
        s0 = lo;
        lo = 0; hi = NN;
        while (lo < hi) {
            int mid = (lo + hi) >> 1;
            int v = is64 ? batch[2 * mid] : batch[mid];
            if (v < g + 1) lo = mid + 1; else hi = mid;
        }
        s1 = lo;
    }
    float acc = 0.f;
    for (int n = s0; n < s1; n++)
        acc += __half2float(d_h2h[(size_t)n * FH + j]);
    sg[j] = acc / (float)max(s1 - s0, 1);
    __syncthreads();
    float a = bm1[j];
#pragma unroll 8
    for (int k = 0; k < FH; k++) a += sg[k] * Wm1[k * FH + j];
    float p = tanhf(a) * Wm2[j];
#pragma unroll
    for (int o = 16; o > 0; o >>= 1)
        p += __shfl_xor_sync(0xFFFFFFFF, p, o);
    if ((j & 31) == 0) red[j >> 5] = p;
    __syncthreads();
    if (j == 0)
        out[g] = red[0] + red[1] + red[2] + red[3] + bm2[0];
}

// ---------------- launch ------------------------------------------------------
extern "C" void kernel_launch(void* const* d_in, const int* in_sizes, int n_in,
                              void* d_out, int out_size) {
    const float* x     = (const float*)d_in[0];
    const int*   ei    = (const int*)d_in[1];
    const int*   batch = (const int*)d_in[2];
    int wb = n_in - 8;
    const float* W1  = (const float*)d_in[wb + 0];
    const float* b1  = (const float*)d_in[wb + 1];
    const float* W2  = (const float*)d_in[wb + 2];
    const float* b2  = (const float*)d_in[wb + 3];
    const float* Wm1 = (const float*)d_in[wb + 4];
    const float* bm1 = (const float*)d_in[wb + 5];
    const float* Wm2 = (const float*)d_in[wb + 6];
    const float* bm2 = (const float*)d_in[wb + 7];
    float* out = (float*)d_out;

    const int smem_l2 = (2 * 128 * SASTRIDE) * 2 + FH * 4;   // 70144 bytes
    cudaFuncSetAttribute(k_l2, cudaFuncAttributeMaxDynamicSharedMemorySize, smem_l2);

    k_init<<<(NN + 255) / 256, 256>>>(ei, W2);
    k_hist<<<(NE / 2 + 255) / 256, 256>>>(ei);
    k_scan<<<NB, 1024>>>(x);
    k_scatter<<<(NE / 2 + 255) / 256, 256>>>(ei);
    k_l1<<<NBLK, 128>>>(W1, b1);
    k_l2<<<NBLK, 256, smem_l2>>>(b2);
    k_poolmlp<<<NG, 128>>>(batch, Wm1, bm1, Wm2, bm2, out);
}